// round 16
// baseline (speedup 1.0000x reference)
#include <cuda_runtime.h>
#include <cuda_bf16.h>
#include <cstdint>
#include <math.h>

#define NN   50000
#define EE   300000
#define FEA  64
#define HD   256
#define GG   256
#define LL   4
#define OUTD 128
#define LH   (LL*HD)   // 1024

// ---------------- scratch (device globals) ---------------------------------
__device__ float g_aggr[(size_t)NN*HD];
__device__ float g_t2  [(size_t)NN*HD];
__device__ float g_h   [(size_t)NN*HD];
__device__ float g_xl  [(size_t)NN*HD];
__device__ float g_sum [HD];
__device__ float g_ssq [HD];
__device__ float g_pooled[GG*LH];
__device__ float g_hh  [GG*HD];
__device__ int   g_src [EE];
__device__ int   g_dst [EE];
__device__ int   g_batch[NN];
__device__ int   g_off [GG+1];
// weights: transposed to [N, K/2], bf16 hi/lo packed pairs (low 16 = even k)
__device__ uint32_t g_bW1h[LL*HD*FEA/2], g_bW1l[LL*HD*FEA/2];
__device__ uint32_t g_bW2h[LL*HD*HD/2],  g_bW2l[LL*HD*HD/2];
__device__ uint32_t g_mW1h[LL*HD*HD/2],  g_mW1l[LL*HD*HD/2];
__device__ uint32_t g_mW2h[LL*HD*HD/2],  g_mW2l[LL*HD*HD/2];
__device__ uint32_t g_f1h [HD*LH/2],     g_f1l [HD*LH/2];
__device__ uint32_t g_f4h [OUTD*HD/2],   g_f4l [OUTD*HD/2];

// ---------------- helpers ---------------------------------------------------
__device__ __forceinline__ void mma_bf16(float* d, const uint32_t* a,
                                         uint32_t b0, uint32_t b1) {
    asm volatile(
        "mma.sync.aligned.m16n8k16.row.col.f32.bf16.bf16.f32 "
        "{%0,%1,%2,%3}, {%4,%5,%6,%7}, {%8,%9}, {%0,%1,%2,%3};"
        : "+f"(d[0]), "+f"(d[1]), "+f"(d[2]), "+f"(d[3])
        : "r"(a[0]), "r"(a[1]), "r"(a[2]), "r"(a[3]), "r"(b0), "r"(b1));
}
__device__ __forceinline__ void ldsm4(uint32_t& r0, uint32_t& r1,
                                      uint32_t& r2, uint32_t& r3,
                                      uint32_t saddr) {
    asm volatile("ldmatrix.sync.aligned.m8n8.x4.shared.b16 {%0,%1,%2,%3}, [%4];"
                 : "=r"(r0), "=r"(r1), "=r"(r2), "=r"(r3) : "r"(saddr));
}
__device__ __forceinline__ uint32_t pack_bf2(__nv_bfloat162 v) {
    return *reinterpret_cast<uint32_t*>(&v);
}
__device__ __forceinline__ void cp_async16(uint32_t saddr, const void* gptr) {
    asm volatile("cp.async.cg.shared.global [%0], [%1], 16;"
                 :: "r"(saddr), "l"(gptr));
}
__device__ __forceinline__ void cp_commit() {
    asm volatile("cp.async.commit_group;");
}
template<int N>
__device__ __forceinline__ void cp_wait() {
    asm volatile("cp.async.wait_group %0;" :: "n"(N));
}
__device__ __forceinline__ void bar_named(int id, int cnt) {
    asm volatile("bar.sync %0, %1;" :: "r"(id), "r"(cnt) : "memory");
}

// ========================= generic GEMM (mlp / fc) ==========================
#define SAK 136
#define SBK 20
#define OFF_AH(b) ((b) * 2176)
#define OFF_AL(b) (4352 + (b) * 2176)
#define OFF_BH(b) (8704 + (b) * 2560)
#define OFF_BL(b) (13824 + (b) * 2560)
#define SMEM_WORDS 18944
#define SMEM_BYTES (SMEM_WORDS * 4)   // 75776

template<bool RELU, bool STATS>
__global__ void __launch_bounds__(256, 2)
bf_gemm(int M, int K,
        const float* __restrict__ A, int lda,
        const uint32_t* __restrict__ Bh, const uint32_t* __restrict__ Bl,
        const float* __restrict__ bias,
        float* __restrict__ C, int ldc)
{
    extern __shared__ uint32_t sm[];

    const int tid  = threadIdx.x;
    const int wid  = tid >> 5;
    const int lane = tid & 31;
    const int warp_m = wid & 1;
    const int warp_n = wid >> 1;
    const int m0 = blockIdx.y * 128;
    const int n0 = blockIdx.x * 128;

    const int ldrow  = tid >> 1;
    const int ldhalf = tid & 1;
    const bool aok = (m0 + ldrow) < M;
    const int K2 = K >> 1;
    const int nch = K >> 5;

    const float*    Ap  = A  + (size_t)(m0 + ldrow) * lda + ldhalf * 16;
    const uint32_t* Bhp = Bh + (size_t)(n0 + ldrow) * K2  + ldhalf * 8;
    const uint32_t* Blp = Bl + (size_t)(n0 + ldrow) * K2  + ldhalf * 8;

    const uint32_t sbase = (uint32_t)__cvta_generic_to_shared(sm);
    const uint32_t bslot = (ldrow * SBK + ldhalf * 8) * 4;

    const int grp = lane >> 2;
    const int qid = lane & 3;

    float acc[4][4][4];
    #pragma unroll
    for (int i = 0; i < 4; i++)
        #pragma unroll
        for (int j = 0; j < 4; j++)
            #pragma unroll
            for (int q = 0; q < 4; q++) acc[i][j][q] = 0.f;

    {
        uint32_t bh_s = sbase + OFF_BH(0) * 4 + bslot;
        uint32_t bl_s = sbase + OFF_BL(0) * 4 + bslot;
        cp_async16(bh_s,      Bhp);
        cp_async16(bh_s + 16, Bhp + 4);
        cp_async16(bl_s,      Blp);
        cp_async16(bl_s + 16, Blp + 4);
        cp_commit();
    }
    float4 ar[4];
    #pragma unroll
    for (int j = 0; j < 4; j++)
        ar[j] = aok ? *(const float4*)(Ap + j * 4)
                    : make_float4(0.f, 0.f, 0.f, 0.f);

    for (int c = 0; c < nch; c++) {
        const int b = c & 1;
        __syncthreads();

        if (c + 1 < nch) {
            uint32_t bh_s = sbase + OFF_BH(b ^ 1) * 4 + bslot;
            uint32_t bl_s = sbase + OFF_BL(b ^ 1) * 4 + bslot;
            const uint32_t* bhp = Bhp + (c + 1) * 16;
            const uint32_t* blp = Blp + (c + 1) * 16;
            cp_async16(bh_s,      bhp);
            cp_async16(bh_s + 16, bhp + 4);
            cp_async16(bl_s,      blp);
            cp_async16(bl_s + 16, blp + 4);
            cp_commit();
        }

        {
            uint32_t* AhS = sm + OFF_AH(b);
            uint32_t* AlS = sm + OFF_AL(b);
            #pragma unroll
            for (int j = 0; j < 4; j++) {
                float4 av = ar[j];
                __nv_bfloat162 h01 = __floats2bfloat162_rn(av.x, av.y);
                __nv_bfloat162 h23 = __floats2bfloat162_rn(av.z, av.w);
                __nv_bfloat162 l01 = __floats2bfloat162_rn(
                    av.x - __low2float(h01), av.y - __high2float(h01));
                __nv_bfloat162 l23 = __floats2bfloat162_rn(
                    av.z - __low2float(h23), av.w - __high2float(h23));
                const int k2 = ldhalf * 8 + 2 * j;
                AhS[(k2    ) * SAK + ldrow] = pack_bf2(h01);
                AhS[(k2 + 1) * SAK + ldrow] = pack_bf2(h23);
                AlS[(k2    ) * SAK + ldrow] = pack_bf2(l01);
                AlS[(k2 + 1) * SAK + ldrow] = pack_bf2(l23);
            }
        }
        if (c + 1 < nch) {
            const float* ap = Ap + (c + 1) * 32;
            #pragma unroll
            for (int j = 0; j < 4; j++)
                ar[j] = aok ? *(const float4*)(ap + j * 4)
                            : make_float4(0.f, 0.f, 0.f, 0.f);
        }

        if (c + 1 < nch) cp_wait<1>(); else cp_wait<0>();
        __syncthreads();

        const uint32_t* AhS = sm + OFF_AH(b);
        const uint32_t* AlS = sm + OFF_AL(b);
        const uint32_t* BhS = sm + OFF_BH(b);
        const uint32_t* BlS = sm + OFF_BL(b);

        #pragma unroll
        for (int s = 0; s < 2; s++) {
            const int k2b = s * 8;
            uint32_t bh0[4], bh1[4], bl0[4], bl1[4];
            #pragma unroll
            for (int nf = 0; nf < 4; nf++) {
                const int nn = warp_n * 32 + nf * 8 + grp;
                bh0[nf] = BhS[nn * SBK + k2b + qid];
                bh1[nf] = BhS[nn * SBK + k2b + qid + 4];
                bl0[nf] = BlS[nn * SBK + k2b + qid];
                bl1[nf] = BlS[nn * SBK + k2b + qid + 4];
            }
            #pragma unroll
            for (int mf = 0; mf < 4; mf++) {
                const int mr = warp_m * 64 + mf * 16 + grp;
                uint32_t ah[4], al[4];
                ah[0] = AhS[(k2b + qid    ) * SAK + mr    ];
                ah[1] = AhS[(k2b + qid    ) * SAK + mr + 8];
                ah[2] = AhS[(k2b + qid + 4) * SAK + mr    ];
                ah[3] = AhS[(k2b + qid + 4) * SAK + mr + 8];
                al[0] = AlS[(k2b + qid    ) * SAK + mr    ];
                al[1] = AlS[(k2b + qid    ) * SAK + mr + 8];
                al[2] = AlS[(k2b + qid + 4) * SAK + mr    ];
                al[3] = AlS[(k2b + qid + 4) * SAK + mr + 8];
                #pragma unroll
                for (int nf = 0; nf < 4; nf++) {
                    mma_bf16(acc[mf][nf], ah, bh0[nf], bh1[nf]);
                    mma_bf16(acc[mf][nf], ah, bl0[nf], bl1[nf]);
                    mma_bf16(acc[mf][nf], al, bh0[nf], bh1[nf]);
                }
            }
        }
    }

    float csum[8], cssq[8];
    if constexpr (STATS) {
        #pragma unroll
        for (int i = 0; i < 8; i++) { csum[i] = 0.f; cssq[i] = 0.f; }
    }
    #pragma unroll
    for (int mf = 0; mf < 4; mf++) {
        #pragma unroll
        for (int half = 0; half < 2; half++) {
            const int row = m0 + warp_m * 64 + mf * 16 + grp + half * 8;
            if (row >= M) continue;
            #pragma unroll
            for (int nf = 0; nf < 4; nf++) {
                const int col = n0 + warp_n * 32 + nf * 8 + 2 * qid;
                float v0 = acc[mf][nf][2*half+0] + bias[col];
                float v1 = acc[mf][nf][2*half+1] + bias[col + 1];
                if (RELU) { v0 = fmaxf(v0, 0.f); v1 = fmaxf(v1, 0.f); }
                *(float2*)(C + (size_t)row * ldc + col) = make_float2(v0, v1);
                if constexpr (STATS) {
                    csum[nf*2+0] += v0; cssq[nf*2+0] += v0 * v0;
                    csum[nf*2+1] += v1; cssq[nf*2+1] += v1 * v1;
                }
            }
        }
    }
    if constexpr (STATS) {
        __syncthreads();
        float* stat = (float*)sm;
        stat[tid & 255] = 0.f;
        __syncthreads();
        #pragma unroll
        for (int nf = 0; nf < 4; nf++)
            #pragma unroll
            for (int j = 0; j < 2; j++) {
                const int cl = warp_n * 32 + nf * 8 + 2 * qid + j;
                atomicAdd(&stat[cl],       csum[nf*2+j]);
                atomicAdd(&stat[128 + cl], cssq[nf*2+j]);
            }
        __syncthreads();
        if (tid < 128)      atomicAdd(&g_sum[n0 + tid],       stat[tid]);
        else                atomicAdd(&g_ssq[n0 + tid - 128], stat[tid]);
    }
}

// == fused bond1+scatter: 64-edge tiles, per-pair B slices, named barriers ====
// Each warp-pair (warp_m 0/1 of one warp_n) owns B rows [64*wn, 64*wn+64):
// loads its slice with its own cp.async groups and syncs with bar.sync(1+wn,64).
// CTA-wide barriers only at A-publish and the stage1->stage2 P transition.
#define SPA 36    // stage1 A stride [row][k2(32)]
#define SPP 132   // P stride        [row][k2(128)]
#define FB_PH   0
#define FB_PL   8448
#define FB_A_H  0
#define FB_A_L  2304
#define FB_BH   16896             // 256*20 words
#define FB_BL   22016
#define FB_WORDS 27136
#define FB_BYTES (FB_WORDS * 4)   // 108544 -> 2 CTAs/SM

__global__ void __launch_bounds__(256, 2)
fused_bond(const float* __restrict__ ea,
           const uint32_t* __restrict__ B1h, const uint32_t* __restrict__ B1l,
           const float* __restrict__ bias1,
           const uint32_t* __restrict__ B2h, const uint32_t* __restrict__ B2l,
           const float* __restrict__ bias2,
           const int* __restrict__ src, const int* __restrict__ dst,
           const float* __restrict__ xg, float* __restrict__ aggr)
{
    extern __shared__ uint32_t sm[];
    const int tid  = threadIdx.x;
    const int wid  = tid >> 5;
    const int lane = tid & 31;
    const int warp_m = wid & 1;     // 2 warps over 64 edges (32 each)
    const int warp_n = wid >> 1;    // 4 warps over N=256 (64 each) = pair id
    const int grp = lane >> 2, qid = lane & 3;
    const int m0 = blockIdx.x * 64;
    const uint32_t sbase = (uint32_t)__cvta_generic_to_shared(sm);
    const int barid = 1 + warp_n;   // named barrier per pair (64 threads)

    // pair-owned B row for loading: 64 threads of the pair, one row each
    const int brow = warp_n * 64 + (tid & 63);
    const uint32_t bslot_h = (uint32_t)(FB_BH + brow * SBK) * 4;
    const uint32_t bslot_l = (uint32_t)(FB_BL + brow * SBK) * 4;

    // issue this pair's slice of chunk cc (matrix row width rw in k2 words)
    auto issue_slice = [&](const uint32_t* Bph, const uint32_t* Bpl,
                           int rw, int cc) {
        const size_t go = (size_t)brow * rw + cc * 16;
        #pragma unroll
        for (int t = 0; t < 4; t++) {
            cp_async16(sbase + bslot_h + t * 16, Bph + go + t * 4);
            cp_async16(sbase + bslot_l + t * 16, Bpl + go + t * 4);
        }
        cp_commit();
    };

    // ---- prologue: pair slice of B1 chunk 0 ----
    issue_slice(B1h, B1l, 32, 0);

    // ---- stage A = edge_attr [64][64] -> bf16 hi/lo, [row][k2] stride SPA --
    {
        const int row = tid >> 2, q = tid & 3;
        const bool eok = (m0 + row) < EE;
        const float* ap = ea + (size_t)(m0 + row) * FEA + q * 16;
        uint32_t* AhS = sm + FB_A_H;
        uint32_t* AlS = sm + FB_A_L;
        #pragma unroll
        for (int j = 0; j < 4; j++) {
            float4 av = eok ? *(const float4*)(ap + j * 4)
                            : make_float4(0.f, 0.f, 0.f, 0.f);
            __nv_bfloat162 h01 = __floats2bfloat162_rn(av.x, av.y);
            __nv_bfloat162 h23 = __floats2bfloat162_rn(av.z, av.w);
            __nv_bfloat162 l01 = __floats2bfloat162_rn(
                av.x - __low2float(h01), av.y - __high2float(h01));
            __nv_bfloat162 l23 = __floats2bfloat162_rn(
                av.z - __low2float(h23), av.w - __high2float(h23));
            const int k2 = q * 8 + 2 * j;
            AhS[row * SPA + k2    ] = pack_bf2(h01);
            AhS[row * SPA + k2 + 1] = pack_bf2(h23);
            AlS[row * SPA + k2    ] = pack_bf2(l01);
            AlS[row * SPA + k2 + 1] = pack_bf2(l23);
        }
    }
    __syncthreads();   // A visible to all pairs

    // ---- ldmatrix per-lane bases ----
    const int a_lrow = (lane & 7) + ((lane >> 3) & 1) * 8;
    const int a_lk4  = (lane >> 4) * 4;
    uint32_t a1BaseH[2], a1BaseL[2], aBaseH[2], aBaseL[2];
    #pragma unroll
    for (int mf = 0; mf < 2; mf++) {
        const int r = warp_m * 32 + mf * 16 + a_lrow;
        a1BaseH[mf] = sbase + (uint32_t)(FB_A_H + r * SPA + a_lk4) * 4;
        a1BaseL[mf] = sbase + (uint32_t)(FB_A_L + r * SPA + a_lk4) * 4;
        aBaseH[mf]  = sbase + (uint32_t)(FB_PH  + r * SPP + a_lk4) * 4;
        aBaseL[mf]  = sbase + (uint32_t)(FB_PL  + r * SPP + a_lk4) * 4;
    }
    const int b_lrow = (lane & 7) + ((lane >> 4) & 1) * 8;
    const int b_lk4  = ((lane >> 3) & 1) * 4;
    uint32_t bOff[4];
    #pragma unroll
    for (int nfp = 0; nfp < 4; nfp++) {
        const int nrow = warp_n * 64 + nfp * 16 + b_lrow;
        bOff[nfp] = (uint32_t)(nrow * SBK + b_lk4) * 4;
    }

    // ---- scatter index prefetch ----
    int pre_sn[4], pre_dn[4];
    #pragma unroll
    for (int mf = 0; mf < 2; mf++)
        #pragma unroll
        for (int half = 0; half < 2; half++) {
            const int e = m0 + warp_m * 32 + mf * 16 + grp + half * 8;
            const int i = mf * 2 + half;
            pre_sn[i] = (e < EE) ? src[e] : 0;
            pre_dn[i] = (e < EE) ? dst[e] : 0;
        }

    float acc[2][8][4];
    #pragma unroll
    for (int i = 0; i < 2; i++)
        #pragma unroll
        for (int j = 0; j < 8; j++)
            #pragma unroll
            for (int q = 0; q < 4; q++) acc[i][j][q] = 0.f;

    const uint32_t bhB = sbase + (uint32_t)FB_BH * 4;
    const uint32_t blB = sbase + (uint32_t)FB_BL * 4;

    #pragma unroll 1
    for (int c = 0; c < 10; c++) {
        const bool s1 = (c < 2);
        const int  cc = s1 ? c : (c - 2);

        cp_wait<0>();              // own pair's slice arrived
        bar_named(barid, 64);      // pair-scope: slice visible to both warps

        #pragma unroll
        for (int s = 0; s < 2; s++) {
            const uint32_t aoff = (uint32_t)(cc * 16 + s * 8) * 4;
            const uint32_t boff = (uint32_t)(s * 8) * 4;
            uint32_t bh0[8], bh1[8], bl0[8], bl1[8];
            #pragma unroll
            for (int nfp = 0; nfp < 4; nfp++) {
                ldsm4(bh0[2*nfp], bh1[2*nfp], bh0[2*nfp+1], bh1[2*nfp+1],
                      bhB + bOff[nfp] + boff);
                ldsm4(bl0[2*nfp], bl1[2*nfp], bl0[2*nfp+1], bl1[2*nfp+1],
                      blB + bOff[nfp] + boff);
            }
            #pragma unroll
            for (int mf = 0; mf < 2; mf++) {
                uint32_t ah[4], al[4];
                ldsm4(ah[0], ah[1], ah[2], ah[3],
                      (s1 ? a1BaseH[mf] : aBaseH[mf]) + aoff);
                ldsm4(al[0], al[1], al[2], al[3],
                      (s1 ? a1BaseL[mf] : aBaseL[mf]) + aoff);
                #pragma unroll
                for (int nf = 0; nf < 8; nf++) {
                    mma_bf16(acc[mf][nf], ah, bh0[nf], bh1[nf]);
                    mma_bf16(acc[mf][nf], ah, bl0[nf], bl1[nf]);
                    mma_bf16(acc[mf][nf], al, bh0[nf], bh1[nf]);
                }
            }
        }

        bar_named(barid, 64);      // pair done reading its slice

        // issue next slice immediately (overlaps other pairs' compute and,
        // at c==1, this CTA's P-write below)
        if (c + 1 < 10) {
            if (c + 1 < 2) issue_slice(B1h, B1l, 32,  c + 1);
            else           issue_slice(B2h, B2l, 128, c + 1 - 2);
        }

        if (c == 1) {
            // stage1 done: write P = relu(acc + b1) over the A region
            __syncthreads();       // ALL pairs finished stage1 A reads
            uint32_t* PhS = sm + FB_PH;
            uint32_t* PlS = sm + FB_PL;
            #pragma unroll
            for (int mf = 0; mf < 2; mf++)
                #pragma unroll
                for (int half = 0; half < 2; half++) {
                    const int rl = warp_m * 32 + mf * 16 + grp + half * 8;
                    #pragma unroll
                    for (int nf = 0; nf < 8; nf++) {
                        const int col = warp_n * 64 + nf * 8 + 2 * qid;
                        float v0 = fmaxf(acc[mf][nf][2*half+0] + bias1[col],     0.f);
                        float v1 = fmaxf(acc[mf][nf][2*half+1] + bias1[col + 1], 0.f);
                        __nv_bfloat162 h = __floats2bfloat162_rn(v0, v1);
                        __nv_bfloat162 lo = __floats2bfloat162_rn(
                            v0 - __low2float(h), v1 - __high2float(h));
                        PhS[rl * SPP + (col >> 1)] = pack_bf2(h);
                        PlS[rl * SPP + (col >> 1)] = pack_bf2(lo);
                    }
                }
            #pragma unroll
            for (int i = 0; i < 2; i++)
                #pragma unroll
                for (int j = 0; j < 8; j++)
                    #pragma unroll
                    for (int q = 0; q < 4; q++) acc[i][j][q] = 0.f;
            __syncthreads();       // P visible to all pairs
        }
    }

    // ---- scatter epilogue: aggr[dst] += relu(x[src] + acc + b2) ----
    #pragma unroll
    for (int mf = 0; mf < 2; mf++)
        #pragma unroll
        for (int half = 0; half < 2; half++) {
            const int e = m0 + warp_m * 32 + mf * 16 + grp + half * 8;
            if (e >= EE) continue;
            const int i = mf * 2 + half;
            const float* xr = xg + (size_t)pre_sn[i] * HD;
            float* ar = aggr + (size_t)pre_dn[i] * HD;
            #pragma unroll
            for (int nf = 0; nf < 8; nf++) {
                const int col = warp_n * 64 + nf * 8 + 2 * qid;
                float2 xv = *(const float2*)(xr + col);
                float v0 = fmaxf(acc[mf][nf][2*half+0] + bias2[col]     + xv.x, 0.f);
                float v1 = fmaxf(acc[mf][nf][2*half+1] + bias2[col + 1] + xv.y, 0.f);
                atomicAdd(ar + col,     v0);
                atomicAdd(ar + col + 1, v1);
            }
        }
}

// ---------------- weight transpose + bf16 hi/lo split + pack ---------------
__global__ void split_pack_k(const float* __restrict__ in,
                             uint32_t* __restrict__ hi, uint32_t* __restrict__ lo,
                             int Lc, int K, int N) {
    int i = blockIdx.x * blockDim.x + threadIdx.x;
    const int K2 = K >> 1;
    int tot = Lc * N * K2;
    if (i >= tot) return;
    int l = i / (N * K2);
    int r = i % (N * K2);
    int n = r / K2, k2 = r % K2;
    float v0 = in[((size_t)l * K + 2*k2    ) * N + n];
    float v1 = in[((size_t)l * K + 2*k2 + 1) * N + n];
    __nv_bfloat162 h = __floats2bfloat162_rn(v0, v1);
    __nv_bfloat162 lw = __floats2bfloat162_rn(v0 - __low2float(h),
                                              v1 - __high2float(h));
    size_t o = ((size_t)l * N + n) * K2 + k2;
    hi[o] = pack_bf2(h);
    lo[o] = pack_bf2(lw);
}

// ---------------- merged setup --------------------------------------------
__global__ void setup_k(const int* __restrict__ ei_raw,
                        const int* __restrict__ batch_raw,
                        const float* __restrict__ xin,
                        const float* __restrict__ eps) {
    bool is64 = (ei_raw[1] == 0) && (ei_raw[3] == 0) && (ei_raw[5] == 0);
    int idx = blockIdx.x * blockDim.x + threadIdx.x;
    int stride = gridDim.x * blockDim.x;
    for (int i = idx; i < EE; i += stride) {
        g_src[i] = is64 ? ei_raw[2*i]        : ei_raw[i];
        g_dst[i] = is64 ? ei_raw[2*(EE + i)] : ei_raw[EE + i];
    }
    for (int i = idx; i < NN; i += stride)
        g_batch[i] = is64 ? batch_raw[2*i] : batch_raw[i];
    float a = 1.0f + eps[0];
    for (int i = idx; i < NN * (HD / 4); i += stride) {
        float4 v = *reinterpret_cast<const float4*>(xin + (size_t)i * 4);
        float4 o = make_float4(a*v.x, a*v.y, a*v.z, a*v.w);
        *reinterpret_cast<float4*>(g_aggr + (size_t)i * 4) = o;
    }
    for (int i = idx; i < GG * LH; i += stride)
        g_pooled[i] = 0.f;
}

__global__ void off_kernel() {
    int g = blockIdx.x * blockDim.x + threadIdx.x;
    if (g > GG) return;
    int lo = 0, hi = NN;
    while (lo < hi) {
        int mid = (lo + hi) >> 1;
        if (g_batch[mid] < g) lo = mid + 1; else hi = mid;
    }
    g_off[g] = lo;
}

// ---------------- batchnorm -------------------------------------------------
__global__ void zero_stats_k() {
    int t = threadIdx.x;
    if (t < HD) { g_sum[t] = 0.f; g_ssq[t] = 0.f; }
}
__global__ void bn_apply_k(const float* __restrict__ gamma,
                           const float* __restrict__ beta, int l,
                           const float* __restrict__ eps, int write_next) {
    int i = blockIdx.x * blockDim.x + threadIdx.x;
    if (i >= NN * HD) return;
    int col = i & (HD - 1);
    int row = i >> 8;
    float mu  = g_sum[col] * (1.0f / NN);
    float var = g_ssq[col] * (1.0f / NN) - mu * mu;
    float sc  = gamma[col] * rsqrtf(var + 1e-5f);
    float val = (g_h[i] - mu) * sc + beta[col];
    atomicAdd(&g_pooled[(size_t)g_batch[row] * LH + l * HD + col], val);
    if (write_next) {
        g_xl[i]   = val;
        g_aggr[i] = (1.0f + eps[l + 1]) * val;
    }
}

__global__ void div_pool_k() {
    int i = blockIdx.x * blockDim.x + threadIdx.x;
    if (i >= GG * LH) return;
    int g = i / LH;
    float cnt = (float)(g_off[g + 1] - g_off[g]);
    g_pooled[i] /= fmaxf(cnt, 1.0f);
}

// ---------------- host-side launchers ----------------------------------------
template<bool RELU, bool STATS>
static void launch_gemm(int M, int K, int Ntot,
                        const float* A, int lda,
                        const uint32_t* Bh, const uint32_t* Bl,
                        const float* bias, float* C, int ldc) {
    static bool attr = false;
    if (!attr) {
        cudaFuncSetAttribute(bf_gemm<RELU,STATS>,
            cudaFuncAttributeMaxDynamicSharedMemorySize, SMEM_BYTES);
        attr = true;
    }
    dim3 grid(Ntot / 128, (M + 127) / 128);
    bf_gemm<RELU,STATS><<<grid, 256, SMEM_BYTES>>>(M, K, A, lda, Bh, Bl, bias, C, ldc);
}

// ---------------- entry ------------------------------------------------------
extern "C" void kernel_launch(void* const* d_in, const int* in_sizes, int n_in,
                              void* d_out, int out_size) {
    const float* x         = (const float*)d_in[0];
    const int*   ei_raw    = (const int*)  d_in[1];
    const float* edge_attr = (const float*)d_in[2];
    const int*   batch_raw = (const int*)  d_in[3];
    const float* bond_W1   = (const float*)d_in[4];
    const float* bond_b1   = (const float*)d_in[5];
    const float* bond_W2   = (const float*)d_in[6];
    const float* bond_b2   = (const float*)d_in[7];
    const float* mlp_W1    = (const float*)d_in[8];
    const float* mlp_b1    = (const float*)d_in[9];
    const float* mlp_W2    = (const float*)d_in[10];
    const float* mlp_b2    = (const float*)d_in[11];
    const float* eps       = (const float*)d_in[12];
    const float* bn_gamma  = (const float*)d_in[13];
    const float* bn_beta   = (const float*)d_in[14];
    const float* fc1_W     = (const float*)d_in[15];
    const float* fc1_b     = (const float*)d_in[16];
    const float* fc4_W     = (const float*)d_in[17];
    const float* fc4_b     = (const float*)d_in[18];
    float* out = (float*)d_out;

    float *aggr, *t2, *h, *xl, *pooled, *hh;
    int *srcp, *dstp;
    cudaGetSymbolAddress((void**)&aggr,   g_aggr);
    cudaGetSymbolAddress((void**)&t2,     g_t2);
    cudaGetSymbolAddress((void**)&h,      g_h);
    cudaGetSymbolAddress((void**)&xl,     g_xl);
    cudaGetSymbolAddress((void**)&pooled, g_pooled);
    cudaGetSymbolAddress((void**)&hh,     g_hh);
    cudaGetSymbolAddress((void**)&srcp,   g_src);
    cudaGetSymbolAddress((void**)&dstp,   g_dst);
    uint32_t *bW1h,*bW1l,*bW2h,*bW2l,*mW1h,*mW1l,*mW2h,*mW2l,*f1h,*f1l,*f4h,*f4l;
    cudaGetSymbolAddress((void**)&bW1h, g_bW1h); cudaGetSymbolAddress((void**)&bW1l, g_bW1l);
    cudaGetSymbolAddress((void**)&bW2h, g_bW2h); cudaGetSymbolAddress((void**)&bW2l, g_bW2l);
    cudaGetSymbolAddress((void**)&mW1h, g_mW1h); cudaGetSymbolAddress((void**)&mW1l, g_mW1l);
    cudaGetSymbolAddress((void**)&mW2h, g_mW2h); cudaGetSymbolAddress((void**)&mW2l, g_mW2l);
    cudaGetSymbolAddress((void**)&f1h,  g_f1h);  cudaGetSymbolAddress((void**)&f1l,  g_f1l);
    cudaGetSymbolAddress((void**)&f4h,  g_f4h);  cudaGetSymbolAddress((void**)&f4l,  g_f4l);

    cudaFuncSetAttribute(fused_bond,
        cudaFuncAttributeMaxDynamicSharedMemorySize, FB_BYTES);

    const int nEtiles = (EE + 63) / 64;

    // index-3 launch = fused_bond (profiled)
    split_pack_k<<<(LL*HD*FEA/2 + 255)/256, 256>>>(bond_W1, bW1h, bW1l, LL, FEA, HD);
    split_pack_k<<<(LL*HD*HD/2  + 255)/256, 256>>>(bond_W2, bW2h, bW2l, LL, HD,  HD);
    setup_k<<<12500, 256>>>(ei_raw, batch_raw, x, eps);
    fused_bond<<<nEtiles, 256, FB_BYTES>>>(
        edge_attr, bW1h, bW1l, bond_b1, bW2h, bW2l, bond_b2,
        srcp, dstp, x, aggr);

    off_kernel<<<2, 256>>>();
    split_pack_k<<<(LL*HD*HD/2  + 255)/256, 256>>>(mlp_W1,  mW1h, mW1l, LL, HD,  HD);
    split_pack_k<<<(LL*HD*HD/2  + 255)/256, 256>>>(mlp_W2,  mW2h, mW2l, LL, HD,  HD);
    split_pack_k<<<(HD*LH/2     + 255)/256, 256>>>(fc1_W,   f1h,  f1l,  1,  LH,  HD);
    split_pack_k<<<(OUTD*HD/2   + 255)/256, 256>>>(fc4_W,   f4h,  f4l,  1,  HD,  OUTD);

    for (int l = 0; l < LL; l++) {
        if (l > 0) {
            fused_bond<<<nEtiles, 256, FB_BYTES>>>(
                edge_attr,
                bW1h + (size_t)l*HD*FEA/2, bW1l + (size_t)l*HD*FEA/2, bond_b1 + l*HD,
                bW2h + (size_t)l*HD*HD/2,  bW2l + (size_t)l*HD*HD/2,  bond_b2 + l*HD,
                srcp, dstp, xl, aggr);
        }

        zero_stats_k<<<1, 256>>>();

        launch_gemm<true,false>(NN, HD, HD, aggr, HD,
            mW1h + (size_t)l*HD*HD/2, mW1l + (size_t)l*HD*HD/2,
            mlp_b1 + l*HD, t2, HD);
        launch_gemm<true,true>(NN, HD, HD, t2, HD,
            mW2h + (size_t)l*HD*HD/2, mW2l + (size_t)l*HD*HD/2,
            mlp_b2 + l*HD, h, HD);

        bn_apply_k<<<(NN*HD + 255)/256, 256>>>(
            bn_gamma + l*HD, bn_beta + l*HD, l, eps, (l < LL-1) ? 1 : 0);
    }

    div_pool_k<<<(GG*LH + 255)/256, 256>>>();

    launch_gemm<true,false>(GG, LH, HD, pooled, LH, f1h, f1l, fc1_b, hh, HD);
    launch_gemm<false,false>(GG, HD, OUTD, hh, HD, f4h, f4l, fc4_b, out, OUTD);
}

// round 17
// speedup vs baseline: 1.1038x; 1.1038x over previous
#include <cuda_runtime.h>
#include <cuda_bf16.h>
#include <cstdint>
#include <math.h>

#define NN   50000
#define EE   300000
#define FEA  64
#define HD   256
#define GG   256
#define LL   4
#define OUTD 128
#define LH   (LL*HD)   // 1024

// ---------------- scratch (device globals) ---------------------------------
__device__ float g_aggr[(size_t)NN*HD];
__device__ float g_t2  [(size_t)NN*HD];
__device__ float g_h   [(size_t)NN*HD];
__device__ float g_xl  [(size_t)NN*HD];
__device__ float g_sum [HD];
__device__ float g_ssq [HD];
__device__ float g_pooled[GG*LH];
__device__ float g_hh  [GG*HD];
__device__ int   g_src [EE];
__device__ int   g_dst [EE];
__device__ int   g_batch[NN];
__device__ int   g_off [GG+1];
// weights: transposed to [N, K/2], bf16 hi/lo packed pairs (low 16 = even k)
__device__ uint32_t g_bW1h[LL*HD*FEA/2], g_bW1l[LL*HD*FEA/2];
__device__ uint32_t g_bW2h[LL*HD*HD/2],  g_bW2l[LL*HD*HD/2];
__device__ uint32_t g_mW1h[LL*HD*HD/2],  g_mW1l[LL*HD*HD/2];
__device__ uint32_t g_mW2h[LL*HD*HD/2],  g_mW2l[LL*HD*HD/2];
__device__ uint32_t g_f1h [HD*LH/2],     g_f1l [HD*LH/2];
__device__ uint32_t g_f4h [OUTD*HD/2],   g_f4l [OUTD*HD/2];

// ---------------- helpers ---------------------------------------------------
__device__ __forceinline__ void mma_bf16(float* d, const uint32_t* a,
                                         uint32_t b0, uint32_t b1) {
    asm volatile(
        "mma.sync.aligned.m16n8k16.row.col.f32.bf16.bf16.f32 "
        "{%0,%1,%2,%3}, {%4,%5,%6,%7}, {%8,%9}, {%0,%1,%2,%3};"
        : "+f"(d[0]), "+f"(d[1]), "+f"(d[2]), "+f"(d[3])
        : "r"(a[0]), "r"(a[1]), "r"(a[2]), "r"(a[3]), "r"(b0), "r"(b1));
}
__device__ __forceinline__ void ldsm4(uint32_t& r0, uint32_t& r1,
                                      uint32_t& r2, uint32_t& r3,
                                      uint32_t saddr) {
    asm volatile("ldmatrix.sync.aligned.m8n8.x4.shared.b16 {%0,%1,%2,%3}, [%4];"
                 : "=r"(r0), "=r"(r1), "=r"(r2), "=r"(r3) : "r"(saddr));
}
__device__ __forceinline__ uint32_t pack_bf2(__nv_bfloat162 v) {
    return *reinterpret_cast<uint32_t*>(&v);
}
__device__ __forceinline__ void cp_async16(uint32_t saddr, const void* gptr) {
    asm volatile("cp.async.cg.shared.global [%0], [%1], 16;"
                 :: "r"(saddr), "l"(gptr));
}
__device__ __forceinline__ void cp_commit() {
    asm volatile("cp.async.commit_group;");
}
template<int N>
__device__ __forceinline__ void cp_wait() {
    asm volatile("cp.async.wait_group %0;" :: "n"(N));
}

// ========================= generic GEMM (mlp / fc) ==========================
#define SAK 136
#define SBK 20
#define OFF_AH(b) ((b) * 2176)
#define OFF_AL(b) (4352 + (b) * 2176)
#define OFF_BH(b) (8704 + (b) * 2560)
#define OFF_BL(b) (13824 + (b) * 2560)
#define SMEM_WORDS 18944
#define SMEM_BYTES (SMEM_WORDS * 4)   // 75776

template<bool RELU, bool STATS>
__global__ void __launch_bounds__(256, 2)
bf_gemm(int M, int K,
        const float* __restrict__ A, int lda,
        const uint32_t* __restrict__ Bh, const uint32_t* __restrict__ Bl,
        const float* __restrict__ bias,
        float* __restrict__ C, int ldc)
{
    extern __shared__ uint32_t sm[];

    const int tid  = threadIdx.x;
    const int wid  = tid >> 5;
    const int lane = tid & 31;
    const int warp_m = wid & 1;
    const int warp_n = wid >> 1;
    const int m0 = blockIdx.y * 128;
    const int n0 = blockIdx.x * 128;

    const int ldrow  = tid >> 1;
    const int ldhalf = tid & 1;
    const bool aok = (m0 + ldrow) < M;
    const int K2 = K >> 1;
    const int nch = K >> 5;

    const float*    Ap  = A  + (size_t)(m0 + ldrow) * lda + ldhalf * 16;
    const uint32_t* Bhp = Bh + (size_t)(n0 + ldrow) * K2  + ldhalf * 8;
    const uint32_t* Blp = Bl + (size_t)(n0 + ldrow) * K2  + ldhalf * 8;

    const uint32_t sbase = (uint32_t)__cvta_generic_to_shared(sm);
    const uint32_t bslot = (ldrow * SBK + ldhalf * 8) * 4;

    const int grp = lane >> 2;
    const int qid = lane & 3;

    // ldmatrix lane mapping for B ([n][k2] stride SBK) — R13-proven pattern
    const int b_lrow = (lane & 7) + ((lane >> 4) & 1) * 8;
    const int b_lk4  = ((lane >> 3) & 1) * 4;
    uint32_t bOff[2];
    #pragma unroll
    for (int nfp = 0; nfp < 2; nfp++) {
        const int nrow = warp_n * 32 + nfp * 16 + b_lrow;
        bOff[nfp] = (uint32_t)(nrow * SBK + b_lk4) * 4;
    }

    float acc[4][4][4];
    #pragma unroll
    for (int i = 0; i < 4; i++)
        #pragma unroll
        for (int j = 0; j < 4; j++)
            #pragma unroll
            for (int q = 0; q < 4; q++) acc[i][j][q] = 0.f;

    {
        uint32_t bh_s = sbase + OFF_BH(0) * 4 + bslot;
        uint32_t bl_s = sbase + OFF_BL(0) * 4 + bslot;
        cp_async16(bh_s,      Bhp);
        cp_async16(bh_s + 16, Bhp + 4);
        cp_async16(bl_s,      Blp);
        cp_async16(bl_s + 16, Blp + 4);
        cp_commit();
    }
    float4 ar[4];
    #pragma unroll
    for (int j = 0; j < 4; j++)
        ar[j] = aok ? *(const float4*)(Ap + j * 4)
                    : make_float4(0.f, 0.f, 0.f, 0.f);

    for (int c = 0; c < nch; c++) {
        const int b = c & 1;
        __syncthreads();

        if (c + 1 < nch) {
            uint32_t bh_s = sbase + OFF_BH(b ^ 1) * 4 + bslot;
            uint32_t bl_s = sbase + OFF_BL(b ^ 1) * 4 + bslot;
            const uint32_t* bhp = Bhp + (c + 1) * 16;
            const uint32_t* blp = Blp + (c + 1) * 16;
            cp_async16(bh_s,      bhp);
            cp_async16(bh_s + 16, bhp + 4);
            cp_async16(bl_s,      blp);
            cp_async16(bl_s + 16, blp + 4);
            cp_commit();
        }

        {
            uint32_t* AhS = sm + OFF_AH(b);
            uint32_t* AlS = sm + OFF_AL(b);
            #pragma unroll
            for (int j = 0; j < 4; j++) {
                float4 av = ar[j];
                __nv_bfloat162 h01 = __floats2bfloat162_rn(av.x, av.y);
                __nv_bfloat162 h23 = __floats2bfloat162_rn(av.z, av.w);
                __nv_bfloat162 l01 = __floats2bfloat162_rn(
                    av.x - __low2float(h01), av.y - __high2float(h01));
                __nv_bfloat162 l23 = __floats2bfloat162_rn(
                    av.z - __low2float(h23), av.w - __high2float(h23));
                const int k2 = ldhalf * 8 + 2 * j;
                AhS[(k2    ) * SAK + ldrow] = pack_bf2(h01);
                AhS[(k2 + 1) * SAK + ldrow] = pack_bf2(h23);
                AlS[(k2    ) * SAK + ldrow] = pack_bf2(l01);
                AlS[(k2 + 1) * SAK + ldrow] = pack_bf2(l23);
            }
        }
        if (c + 1 < nch) {
            const float* ap = Ap + (c + 1) * 32;
            #pragma unroll
            for (int j = 0; j < 4; j++)
                ar[j] = aok ? *(const float4*)(ap + j * 4)
                            : make_float4(0.f, 0.f, 0.f, 0.f);
        }

        if (c + 1 < nch) cp_wait<1>(); else cp_wait<0>();
        __syncthreads();

        const uint32_t* AhS = sm + OFF_AH(b);
        const uint32_t* AlS = sm + OFF_AL(b);
        const uint32_t bhB = sbase + (uint32_t)OFF_BH(b) * 4;
        const uint32_t blB = sbase + (uint32_t)OFF_BL(b) * 4;

        #pragma unroll
        for (int s = 0; s < 2; s++) {
            const int k2b = s * 8;
            const uint32_t boff = (uint32_t)k2b * 4;
            uint32_t bh0[4], bh1[4], bl0[4], bl1[4];
            #pragma unroll
            for (int nfp = 0; nfp < 2; nfp++) {
                ldsm4(bh0[2*nfp], bh1[2*nfp], bh0[2*nfp+1], bh1[2*nfp+1],
                      bhB + bOff[nfp] + boff);
                ldsm4(bl0[2*nfp], bl1[2*nfp], bl0[2*nfp+1], bl1[2*nfp+1],
                      blB + bOff[nfp] + boff);
            }
            #pragma unroll
            for (int mf = 0; mf < 4; mf++) {
                const int mr = warp_m * 64 + mf * 16 + grp;
                uint32_t ah[4], al[4];
                ah[0] = AhS[(k2b + qid    ) * SAK + mr    ];
                ah[1] = AhS[(k2b + qid    ) * SAK + mr + 8];
                ah[2] = AhS[(k2b + qid + 4) * SAK + mr    ];
                ah[3] = AhS[(k2b + qid + 4) * SAK + mr + 8];
                al[0] = AlS[(k2b + qid    ) * SAK + mr    ];
                al[1] = AlS[(k2b + qid    ) * SAK + mr + 8];
                al[2] = AlS[(k2b + qid + 4) * SAK + mr    ];
                al[3] = AlS[(k2b + qid + 4) * SAK + mr + 8];
                #pragma unroll
                for (int nf = 0; nf < 4; nf++) {
                    mma_bf16(acc[mf][nf], ah, bh0[nf], bh1[nf]);
                    mma_bf16(acc[mf][nf], ah, bl0[nf], bl1[nf]);
                    mma_bf16(acc[mf][nf], al, bh0[nf], bh1[nf]);
                }
            }
        }
    }

    float csum[8], cssq[8];
    if constexpr (STATS) {
        #pragma unroll
        for (int i = 0; i < 8; i++) { csum[i] = 0.f; cssq[i] = 0.f; }
    }
    #pragma unroll
    for (int mf = 0; mf < 4; mf++) {
        #pragma unroll
        for (int half = 0; half < 2; half++) {
            const int row = m0 + warp_m * 64 + mf * 16 + grp + half * 8;
            if (row >= M) continue;
            #pragma unroll
            for (int nf = 0; nf < 4; nf++) {
                const int col = n0 + warp_n * 32 + nf * 8 + 2 * qid;
                float v0 = acc[mf][nf][2*half+0] + bias[col];
                float v1 = acc[mf][nf][2*half+1] + bias[col + 1];
                if (RELU) { v0 = fmaxf(v0, 0.f); v1 = fmaxf(v1, 0.f); }
                *(float2*)(C + (size_t)row * ldc + col) = make_float2(v0, v1);
                if constexpr (STATS) {
                    csum[nf*2+0] += v0; cssq[nf*2+0] += v0 * v0;
                    csum[nf*2+1] += v1; cssq[nf*2+1] += v1 * v1;
                }
            }
        }
    }
    if constexpr (STATS) {
        __syncthreads();
        float* stat = (float*)sm;
        stat[tid & 255] = 0.f;
        __syncthreads();
        #pragma unroll
        for (int nf = 0; nf < 4; nf++)
            #pragma unroll
            for (int j = 0; j < 2; j++) {
                const int cl = warp_n * 32 + nf * 8 + 2 * qid + j;
                atomicAdd(&stat[cl],       csum[nf*2+j]);
                atomicAdd(&stat[128 + cl], cssq[nf*2+j]);
            }
        __syncthreads();
        if (tid < 128)      atomicAdd(&g_sum[n0 + tid],       stat[tid]);
        else                atomicAdd(&g_ssq[n0 + tid - 128], stat[tid]);
    }
}

// ====== fused bond1+scatter (R15-proven: 64-edge tiles, hi/lo split pipe) ====
#define SPA 36    // stage1 A stride [row][k2(32)]
#define SPP 132   // P stride        [row][k2(128)]
#define FB_PH   0
#define FB_PL   8448
#define FB_A_H  0
#define FB_A_L  2304
#define FB_B0   16896             // hi items
#define FB_B1b  22016             // lo items
#define FB_WORDS 27136
#define FB_BYTES (FB_WORDS * 4)   // 108544 -> 2 CTAs/SM

__global__ void __launch_bounds__(256, 2)
fused_bond(const float* __restrict__ ea,
           const uint32_t* __restrict__ B1h, const uint32_t* __restrict__ B1l,
           const float* __restrict__ bias1,
           const uint32_t* __restrict__ B2h, const uint32_t* __restrict__ B2l,
           const float* __restrict__ bias2,
           const int* __restrict__ src, const int* __restrict__ dst,
           const float* __restrict__ xg, float* __restrict__ aggr)
{
    extern __shared__ uint32_t sm[];
    const int tid  = threadIdx.x;
    const int wid  = tid >> 5;
    const int lane = tid & 31;
    const int warp_m = wid & 1;     // 2 warps over 64 edges (32 each)
    const int warp_n = wid >> 1;    // 4 warps over N=256 (64 each)
    const int grp = lane >> 2, qid = lane & 3;
    const int m0 = blockIdx.x * 64;
    const uint32_t sbase = (uint32_t)__cvta_generic_to_shared(sm);

    const int ld_row  = tid >> 2;
    const int ld_part = (tid & 3) * 4;

    auto issue_item = [&](const uint32_t* Bp, int rw, int cc, uint32_t bufOff) {
        #pragma unroll
        for (int t = 0; t < 4; t++) {
            const int row = ld_row + 64 * t;
            cp_async16(sbase + (bufOff + row * SBK + ld_part) * 4,
                       Bp + (size_t)row * rw + cc * 16 + ld_part);
        }
        cp_commit();
    };

    issue_item(B1h, 32, 0, FB_B0);
    issue_item(B1l, 32, 0, FB_B1b);

    {
        const int row = tid >> 2, q = tid & 3;
        const bool eok = (m0 + row) < EE;
        const float* ap = ea + (size_t)(m0 + row) * FEA + q * 16;
        uint32_t* AhS = sm + FB_A_H;
        uint32_t* AlS = sm + FB_A_L;
        #pragma unroll
        for (int j = 0; j < 4; j++) {
            float4 av = eok ? *(const float4*)(ap + j * 4)
                            : make_float4(0.f, 0.f, 0.f, 0.f);
            __nv_bfloat162 h01 = __floats2bfloat162_rn(av.x, av.y);
            __nv_bfloat162 h23 = __floats2bfloat162_rn(av.z, av.w);
            __nv_bfloat162 l01 = __floats2bfloat162_rn(
                av.x - __low2float(h01), av.y - __high2float(h01));
            __nv_bfloat162 l23 = __floats2bfloat162_rn(
                av.z - __low2float(h23), av.w - __high2float(h23));
            const int k2 = q * 8 + 2 * j;
            AhS[row * SPA + k2    ] = pack_bf2(h01);
            AhS[row * SPA + k2 + 1] = pack_bf2(h23);
            AlS[row * SPA + k2    ] = pack_bf2(l01);
            AlS[row * SPA + k2 + 1] = pack_bf2(l23);
        }
    }

    const int a_lrow = (lane & 7) + ((lane >> 3) & 1) * 8;
    const int a_lk4  = (lane >> 4) * 4;
    uint32_t a1BaseH[2], a1BaseL[2], aBaseH[2], aBaseL[2];
    #pragma unroll
    for (int mf = 0; mf < 2; mf++) {
        const int r = warp_m * 32 + mf * 16 + a_lrow;
        a1BaseH[mf] = sbase + (uint32_t)(FB_A_H + r * SPA + a_lk4) * 4;
        a1BaseL[mf] = sbase + (uint32_t)(FB_A_L + r * SPA + a_lk4) * 4;
        aBaseH[mf]  = sbase + (uint32_t)(FB_PH  + r * SPP + a_lk4) * 4;
        aBaseL[mf]  = sbase + (uint32_t)(FB_PL  + r * SPP + a_lk4) * 4;
    }
    const int b_lrow = (lane & 7) + ((lane >> 4) & 1) * 8;
    const int b_lk4  = ((lane >> 3) & 1) * 4;
    uint32_t bOff[4];
    #pragma unroll
    for (int nfp = 0; nfp < 4; nfp++) {
        const int nrow = warp_n * 64 + nfp * 16 + b_lrow;
        bOff[nfp] = (uint32_t)(nrow * SBK + b_lk4) * 4;
    }

    int pre_sn[4], pre_dn[4];
    #pragma unroll
    for (int mf = 0; mf < 2; mf++)
        #pragma unroll
        for (int half = 0; half < 2; half++) {
            const int e = m0 + warp_m * 32 + mf * 16 + grp + half * 8;
            const int i = mf * 2 + half;
            pre_sn[i] = (e < EE) ? src[e] : 0;
            pre_dn[i] = (e < EE) ? dst[e] : 0;
        }

    float acc[2][8][4];
    #pragma unroll
    for (int i = 0; i < 2; i++)
        #pragma unroll
        for (int j = 0; j < 8; j++)
            #pragma unroll
            for (int q = 0; q < 4; q++) acc[i][j][q] = 0.f;

    const uint32_t b0B = sbase + (uint32_t)FB_B0  * 4;
    const uint32_t b1B = sbase + (uint32_t)FB_B1b * 4;

    #pragma unroll 1
    for (int c = 0; c < 10; c++) {
        const bool s1 = (c < 2);
        const int  cc = s1 ? c : (c - 2);

        // ======== HI phase: item 2c in buf0 ========
        cp_wait<1>();
        __syncthreads();
        #pragma unroll
        for (int s = 0; s < 2; s++) {
            const uint32_t aoff = (uint32_t)(cc * 16 + s * 8) * 4;
            const uint32_t boff = (uint32_t)(s * 8) * 4;
            uint32_t bh0[8], bh1[8];
            #pragma unroll
            for (int nfp = 0; nfp < 4; nfp++)
                ldsm4(bh0[2*nfp], bh1[2*nfp], bh0[2*nfp+1], bh1[2*nfp+1],
                      b0B + bOff[nfp] + boff);
            #pragma unroll
            for (int mf = 0; mf < 2; mf++) {
                uint32_t ah[4], al[4];
                ldsm4(ah[0], ah[1], ah[2], ah[3],
                      (s1 ? a1BaseH[mf] : aBaseH[mf]) + aoff);
                ldsm4(al[0], al[1], al[2], al[3],
                      (s1 ? a1BaseL[mf] : aBaseL[mf]) + aoff);
                #pragma unroll
                for (int nf = 0; nf < 8; nf++) {
                    mma_bf16(acc[mf][nf], ah, bh0[nf], bh1[nf]);
                    mma_bf16(acc[mf][nf], al, bh0[nf], bh1[nf]);
                }
            }
        }
        __syncthreads();
        if (c + 1 < 10) {
            if (c + 1 < 2) issue_item(B1h, 32,  c + 1,     FB_B0);
            else           issue_item(B2h, 128, c + 1 - 2, FB_B0);
        }

        // ======== LO phase: item 2c+1 in buf1 ========
        if (c == 9) cp_wait<0>(); else cp_wait<1>();
        __syncthreads();
        #pragma unroll
        for (int s = 0; s < 2; s++) {
            const uint32_t aoff = (uint32_t)(cc * 16 + s * 8) * 4;
            const uint32_t boff = (uint32_t)(s * 8) * 4;
            uint32_t bl0[8], bl1[8];
            #pragma unroll
            for (int nfp = 0; nfp < 4; nfp++)
                ldsm4(bl0[2*nfp], bl1[2*nfp], bl0[2*nfp+1], bl1[2*nfp+1],
                      b1B + bOff[nfp] + boff);
            #pragma unroll
            for (int mf = 0; mf < 2; mf++) {
                uint32_t ah[4];
                ldsm4(ah[0], ah[1], ah[2], ah[3],
                      (s1 ? a1BaseH[mf] : aBaseH[mf]) + aoff);
                #pragma unroll
                for (int nf = 0; nf < 8; nf++)
                    mma_bf16(acc[mf][nf], ah, bl0[nf], bl1[nf]);
            }
        }
        __syncthreads();
        if (c + 1 < 10) {
            if (c + 1 < 2) issue_item(B1l, 32,  c + 1,     FB_B1b);
            else           issue_item(B2l, 128, c + 1 - 2, FB_B1b);
        }

        if (c == 1) {
            uint32_t* PhS = sm + FB_PH;
            uint32_t* PlS = sm + FB_PL;
            #pragma unroll
            for (int mf = 0; mf < 2; mf++)
                #pragma unroll
                for (int half = 0; half < 2; half++) {
                    const int rl = warp_m * 32 + mf * 16 + grp + half * 8;
                    #pragma unroll
                    for (int nf = 0; nf < 8; nf++) {
                        const int col = warp_n * 64 + nf * 8 + 2 * qid;
                        float v0 = fmaxf(acc[mf][nf][2*half+0] + bias1[col],     0.f);
                        float v1 = fmaxf(acc[mf][nf][2*half+1] + bias1[col + 1], 0.f);
                        __nv_bfloat162 h = __floats2bfloat162_rn(v0, v1);
                        __nv_bfloat162 lo = __floats2bfloat162_rn(
                            v0 - __low2float(h), v1 - __high2float(h));
                        PhS[rl * SPP + (col >> 1)] = pack_bf2(h);
                        PlS[rl * SPP + (col >> 1)] = pack_bf2(lo);
                    }
                }
            #pragma unroll
            for (int i = 0; i < 2; i++)
                #pragma unroll
                for (int j = 0; j < 8; j++)
                    #pragma unroll
                    for (int q = 0; q < 4; q++) acc[i][j][q] = 0.f;
        }
    }

    // ---- scatter epilogue ----
    #pragma unroll
    for (int mf = 0; mf < 2; mf++)
        #pragma unroll
        for (int half = 0; half < 2; half++) {
            const int e = m0 + warp_m * 32 + mf * 16 + grp + half * 8;
            if (e >= EE) continue;
            const int i = mf * 2 + half;
            const float* xr = xg + (size_t)pre_sn[i] * HD;
            float* ar = aggr + (size_t)pre_dn[i] * HD;
            #pragma unroll
            for (int nf = 0; nf < 8; nf++) {
                const int col = warp_n * 64 + nf * 8 + 2 * qid;
                float2 xv = *(const float2*)(xr + col);
                float v0 = fmaxf(acc[mf][nf][2*half+0] + bias2[col]     + xv.x, 0.f);
                float v1 = fmaxf(acc[mf][nf][2*half+1] + bias2[col + 1] + xv.y, 0.f);
                atomicAdd(ar + col,     v0);
                atomicAdd(ar + col + 1, v1);
            }
        }
}

// ---------------- weight transpose + bf16 hi/lo split + pack ---------------
__global__ void split_pack_k(const float* __restrict__ in,
                             uint32_t* __restrict__ hi, uint32_t* __restrict__ lo,
                             int Lc, int K, int N) {
    int i = blockIdx.x * blockDim.x + threadIdx.x;
    const int K2 = K >> 1;
    int tot = Lc * N * K2;
    if (i >= tot) return;
    int l = i / (N * K2);
    int r = i % (N * K2);
    int n = r / K2, k2 = r % K2;
    float v0 = in[((size_t)l * K + 2*k2    ) * N + n];
    float v1 = in[((size_t)l * K + 2*k2 + 1) * N + n];
    __nv_bfloat162 h = __floats2bfloat162_rn(v0, v1);
    __nv_bfloat162 lw = __floats2bfloat162_rn(v0 - __low2float(h),
                                              v1 - __high2float(h));
    size_t o = ((size_t)l * N + n) * K2 + k2;
    hi[o] = pack_bf2(h);
    lo[o] = pack_bf2(lw);
}

// ---------------- merged setup --------------------------------------------
__global__ void setup_k(const int* __restrict__ ei_raw,
                        const int* __restrict__ batch_raw,
                        const float* __restrict__ xin,
                        const float* __restrict__ eps) {
    bool is64 = (ei_raw[1] == 0) && (ei_raw[3] == 0) && (ei_raw[5] == 0);
    int idx = blockIdx.x * blockDim.x + threadIdx.x;
    int stride = gridDim.x * blockDim.x;
    for (int i = idx; i < EE; i += stride) {
        g_src[i] = is64 ? ei_raw[2*i]        : ei_raw[i];
        g_dst[i] = is64 ? ei_raw[2*(EE + i)] : ei_raw[EE + i];
    }
    for (int i = idx; i < NN; i += stride)
        g_batch[i] = is64 ? batch_raw[2*i] : batch_raw[i];
    float a = 1.0f + eps[0];
    for (int i = idx; i < NN * (HD / 4); i += stride) {
        float4 v = *reinterpret_cast<const float4*>(xin + (size_t)i * 4);
        float4 o = make_float4(a*v.x, a*v.y, a*v.z, a*v.w);
        *reinterpret_cast<float4*>(g_aggr + (size_t)i * 4) = o;
    }
    for (int i = idx; i < GG * LH; i += stride)
        g_pooled[i] = 0.f;
}

__global__ void off_kernel() {
    int g = blockIdx.x * blockDim.x + threadIdx.x;
    if (g > GG) return;
    int lo = 0, hi = NN;
    while (lo < hi) {
        int mid = (lo + hi) >> 1;
        if (g_batch[mid] < g) lo = mid + 1; else hi = mid;
    }
    g_off[g] = lo;
}

// ---------------- batchnorm -------------------------------------------------
__global__ void zero_stats_k() {
    int t = threadIdx.x;
    if (t < HD) { g_sum[t] = 0.f; g_ssq[t] = 0.f; }
}
__global__ void bn_apply_k(const float* __restrict__ gamma,
                           const float* __restrict__ beta, int l,
                           const float* __restrict__ eps, int write_next) {
    int i = blockIdx.x * blockDim.x + threadIdx.x;
    if (i >= NN * HD) return;
    int col = i & (HD - 1);
    int row = i >> 8;
    float mu  = g_sum[col] * (1.0f / NN);
    float var = g_ssq[col] * (1.0f / NN) - mu * mu;
    float sc  = gamma[col] * rsqrtf(var + 1e-5f);
    float val = (g_h[i] - mu) * sc + beta[col];
    atomicAdd(&g_pooled[(size_t)g_batch[row] * LH + l * HD + col], val);
    if (write_next) {
        g_xl[i]   = val;
        g_aggr[i] = (1.0f + eps[l + 1]) * val;
    }
}

__global__ void div_pool_k() {
    int i = blockIdx.x * blockDim.x + threadIdx.x;
    if (i >= GG * LH) return;
    int g = i / LH;
    float cnt = (float)(g_off[g + 1] - g_off[g]);
    g_pooled[i] /= fmaxf(cnt, 1.0f);
}

// ---------------- host-side launchers ----------------------------------------
template<bool RELU, bool STATS>
static void launch_gemm(int M, int K, int Ntot,
                        const float* A, int lda,
                        const uint32_t* Bh, const uint32_t* Bl,
                        const float* bias, float* C, int ldc) {
    static bool attr = false;
    if (!attr) {
        cudaFuncSetAttribute(bf_gemm<RELU,STATS>,
            cudaFuncAttributeMaxDynamicSharedMemorySize, SMEM_BYTES);
        attr = true;
    }
    dim3 grid(Ntot / 128, (M + 127) / 128);
    bf_gemm<RELU,STATS><<<grid, 256, SMEM_BYTES>>>(M, K, A, lda, Bh, Bl, bias, C, ldc);
}

// ---------------- entry ------------------------------------------------------
extern "C" void kernel_launch(void* const* d_in, const int* in_sizes, int n_in,
                              void* d_out, int out_size) {
    const float* x         = (const float*)d_in[0];
    const int*   ei_raw    = (const int*)  d_in[1];
    const float* edge_attr = (const float*)d_in[2];
    const int*   batch_raw = (const int*)  d_in[3];
    const float* bond_W1   = (const float*)d_in[4];
    const float* bond_b1   = (const float*)d_in[5];
    const float* bond_W2   = (const float*)d_in[6];
    const float* bond_b2   = (const float*)d_in[7];
    const float* mlp_W1    = (const float*)d_in[8];
    const float* mlp_b1    = (const float*)d_in[9];
    const float* mlp_W2    = (const float*)d_in[10];
    const float* mlp_b2    = (const float*)d_in[11];
    const float* eps       = (const float*)d_in[12];
    const float* bn_gamma  = (const float*)d_in[13];
    const float* bn_beta   = (const float*)d_in[14];
    const float* fc1_W     = (const float*)d_in[15];
    const float* fc1_b     = (const float*)d_in[16];
    const float* fc4_W     = (const float*)d_in[17];
    const float* fc4_b     = (const float*)d_in[18];
    float* out = (float*)d_out;

    float *aggr, *t2, *h, *xl, *pooled, *hh;
    int *srcp, *dstp;
    cudaGetSymbolAddress((void**)&aggr,   g_aggr);
    cudaGetSymbolAddress((void**)&t2,     g_t2);
    cudaGetSymbolAddress((void**)&h,      g_h);
    cudaGetSymbolAddress((void**)&xl,     g_xl);
    cudaGetSymbolAddress((void**)&pooled, g_pooled);
    cudaGetSymbolAddress((void**)&hh,     g_hh);
    cudaGetSymbolAddress((void**)&srcp,   g_src);
    cudaGetSymbolAddress((void**)&dstp,   g_dst);
    uint32_t *bW1h,*bW1l,*bW2h,*bW2l,*mW1h,*mW1l,*mW2h,*mW2l,*f1h,*f1l,*f4h,*f4l;
    cudaGetSymbolAddress((void**)&bW1h, g_bW1h); cudaGetSymbolAddress((void**)&bW1l, g_bW1l);
    cudaGetSymbolAddress((void**)&bW2h, g_bW2h); cudaGetSymbolAddress((void**)&bW2l, g_bW2l);
    cudaGetSymbolAddress((void**)&mW1h, g_mW1h); cudaGetSymbolAddress((void**)&mW1l, g_mW1l);
    cudaGetSymbolAddress((void**)&mW2h, g_mW2h); cudaGetSymbolAddress((void**)&mW2l, g_mW2l);
    cudaGetSymbolAddress((void**)&f1h,  g_f1h);  cudaGetSymbolAddress((void**)&f1l,  g_f1l);
    cudaGetSymbolAddress((void**)&f4h,  g_f4h);  cudaGetSymbolAddress((void**)&f4l,  g_f4l);

    cudaFuncSetAttribute(fused_bond,
        cudaFuncAttributeMaxDynamicSharedMemorySize, FB_BYTES);

    const int nEtiles = (EE + 63) / 64;

    // index-3 launch = fused_bond (profiled)
    split_pack_k<<<(LL*HD*FEA/2 + 255)/256, 256>>>(bond_W1, bW1h, bW1l, LL, FEA, HD);
    split_pack_k<<<(LL*HD*HD/2  + 255)/256, 256>>>(bond_W2, bW2h, bW2l, LL, HD,  HD);
    setup_k<<<12500, 256>>>(ei_raw, batch_raw, x, eps);
    fused_bond<<<nEtiles, 256, FB_BYTES>>>(
        edge_attr, bW1h, bW1l, bond_b1, bW2h, bW2l, bond_b2,
        srcp, dstp, x, aggr);

    off_kernel<<<2, 256>>>();
    split_pack_k<<<(LL*HD*HD/2  + 255)/256, 256>>>(mlp_W1,  mW1h, mW1l, LL, HD,  HD);
    split_pack_k<<<(LL*HD*HD/2  + 255)/256, 256>>>(mlp_W2,  mW2h, mW2l, LL, HD,  HD);
    split_pack_k<<<(HD*LH/2     + 255)/256, 256>>>(fc1_W,   f1h,  f1l,  1,  LH,  HD);
    split_pack_k<<<(OUTD*HD/2   + 255)/256, 256>>>(fc4_W,   f4h,  f4l,  1,  HD,  OUTD);

    for (int l = 0; l < LL; l++) {
        if (l > 0) {
            fused_bond<<<nEtiles, 256, FB_BYTES>>>(
                edge_attr,
                bW1h + (size_t)l*HD*FEA/2, bW1l + (size_t)l*HD*FEA/2, bond_b1 + l*HD,
                bW2h + (size_t)l*HD*HD/2,  bW2l + (size_t)l*HD*HD/2,  bond_b2 + l*HD,
                srcp, dstp, xl, aggr);
        }

        zero_stats_k<<<1, 256>>>();

        launch_gemm<true,false>(NN, HD, HD, aggr, HD,
            mW1h + (size_t)l*HD*HD/2, mW1l + (size_t)l*HD*HD/2,
            mlp_b1 + l*HD, t2, HD);
        launch_gemm<true,true>(NN, HD, HD, t2, HD,
            mW2h + (size_t)l*HD*HD/2, mW2l + (size_t)l*HD*HD/2,
            mlp_b2 + l*HD, h, HD);

        bn_apply_k<<<(NN*HD + 255)/256, 256>>>(
            bn_gamma + l*HD, bn_beta + l*HD, l, eps, (l < LL-1) ? 1 : 0);
    }

    div_pool_k<<<(GG*LH + 255)/256, 256>>>();

    launch_gemm<true,false>(GG, LH, HD, pooled, LH, f1h, f1l, fc1_b, hh, HD);
    launch_gemm<false,false>(GG, HD, OUTD, hh, HD, f4h, f4l, fc4_b, out, OUTD);
}